// round 1
// baseline (speedup 1.0000x reference)
#include <cuda_runtime.h>
#include <math.h>

#define B_  4
#define C_  64
#define HH  128
#define WW  128
#define F_  5
#define L_  512
#define NH_ 128

// ---------------- device scratch ----------------
__device__ float g_mu[B_*F_*L_];                 // relu(fc(codes))         [b,f,l]
__device__ unsigned char g_rmap[B_*HH*WW];       // region index per pixel (5 = none)
__device__ float g_Tg[B_*9*F_*C_];               // [b][tap][f][c]
__device__ float g_Tb[B_*9*F_*C_];
__device__ float g_actv[(size_t)B_*NH_*HH*WW];   // SPADE shared activation (33.5MB)
__device__ float g_mean[B_*C_];
__device__ float g_rsig[B_*C_];

// ---------------- mu = relu(codes @ fc_w^T + fc_b) ----------------
// grid 20 (b*5+f), 512 threads (k)
__global__ void mu_kernel(const float* __restrict__ codes,
                          const float* __restrict__ fc_w,
                          const float* __restrict__ fc_b) {
    __shared__ float sc[L_];
    int bf = blockIdx.x;
    int f = bf % F_;
    int k = threadIdx.x;
    sc[k] = codes[bf*L_ + k];
    __syncthreads();
    const float* wp = fc_w + ((size_t)f*L_ + k)*L_;
    float acc = fc_b[f*L_ + k];
    #pragma unroll 4
    for (int l = 0; l < L_; ++l) acc = fmaf(sc[l], wp[l], acc);
    g_mu[bf*L_ + k] = fmaxf(acc, 0.f);
}

// ---------------- region map: last j with segmap>0, else 5 ----------------
__global__ void region_kernel(const float* __restrict__ seg) {
    int p = blockIdx.x*256 + threadIdx.x;
    if (p >= B_*HH*WW) return;
    int b = p >> 14, pix = p & 16383;
    int r = 5;
    #pragma unroll
    for (int j = 0; j < F_; ++j)
        if (seg[(b*F_ + j)*16384 + pix] > 0.f) r = j;
    g_rmap[p] = (unsigned char)r;
}

// ---------------- tables T[b,tap,f,c] = sum_l convW[c,l,tap]*mu[b,f,l] ----------------
// one warp per entry; 2 tables * 4*9*5*64 = 23040 entries; grid 2880 x 256
__global__ void table_kernel(const float* __restrict__ cgw,
                             const float* __restrict__ cbw) {
    int gt = blockIdx.x*256 + threadIdx.x;
    int e = gt >> 5, lane = gt & 31;
    int tbl = e / 11520; int r = e - tbl*11520;
    int b = r / 2880;    int r2 = r - b*2880;
    int tap = r2 / 320;  int r3 = r2 - tap*320;
    int f = r3 >> 6;     int c = r3 & 63;
    int dy = tap / 3, dx = tap - dy*3;
    const float* w = tbl ? cbw : cgw;
    const float* m = g_mu + (b*F_ + f)*L_;
    float s = 0.f;
    for (int l = lane; l < L_; l += 32)
        s = fmaf(w[(((size_t)c*L_ + l)*3 + dy)*3 + dx], m[l], s);
    #pragma unroll
    for (int o = 16; o > 0; o >>= 1) s += __shfl_down_sync(0xffffffffu, s, o);
    if (lane == 0)
        (tbl ? g_Tb : g_Tg)[((b*9 + tap)*F_ + f)*64 + c] = s;
}

// ---------------- instance norm stats ----------------
__global__ void stats_kernel(const float* __restrict__ x) {
    int bc = blockIdx.x;
    const float* p = x + (size_t)bc*16384;
    float s = 0.f, s2 = 0.f;
    for (int i = threadIdx.x; i < 16384; i += 256) {
        float v = p[i]; s += v; s2 = fmaf(v, v, s2);
    }
    __shared__ float sh1[256], sh2[256];
    sh1[threadIdx.x] = s; sh2[threadIdx.x] = s2;
    __syncthreads();
    for (int o = 128; o > 0; o >>= 1) {
        if (threadIdx.x < o) { sh1[threadIdx.x] += sh1[threadIdx.x+o]; sh2[threadIdx.x] += sh2[threadIdx.x+o]; }
        __syncthreads();
    }
    if (threadIdx.x == 0) {
        float m = sh1[0] * (1.f/16384.f);
        float var = sh2[0] * (1.f/16384.f) - m*m;
        g_mean[bc] = m;
        g_rsig[bc] = rsqrtf(var + 1e-5f);
    }
}

// ---------------- SPADE shared conv: mask(3) -> actv(128), relu ----------------
__global__ void sconv_kernel(const float* __restrict__ mask,
                             const float* __restrict__ w,
                             const float* __restrict__ bias) {
    int idx = blockIdx.x*256 + threadIdx.x;
    if (idx >= B_*NH_*HH*WW) return;
    int x = idx & 127, y = (idx >> 7) & 127, nh = (idx >> 14) & 127, b = idx >> 21;
    float acc = __ldg(&bias[nh]);
    const float* wp = w + nh*27;
    const float* mp = mask + (size_t)b*3*16384;
    #pragma unroll
    for (int i = 0; i < 3; ++i) {
        #pragma unroll
        for (int dy = 0; dy < 3; ++dy) {
            int gy = y + dy - 1;
            if ((unsigned)gy >= 128u) continue;
            #pragma unroll
            for (int dx = 0; dx < 3; ++dx) {
                int gx = x + dx - 1;
                if ((unsigned)gx >= 128u) continue;
                acc = fmaf(__ldg(&mp[i*16384 + (gy<<7) + gx]),
                           __ldg(&wp[i*9 + dy*3 + dx]), acc);
            }
        }
    }
    g_actv[idx] = fmaxf(acc, 0.f);
}

// ---------------- fused: spade gamma/beta convs + table gather + blend + denorm --------
// block = 8x16 pixel tile, 256 threads: 16 cout-groups (8 couts of 128) x 16 pixel-groups (8 px)
// smem (floats): sW[16*9*132]=19008 | sA[16*10*20]=3200 | sTg 2880 | sTb 2880 | sR 64
#define OFF_A  19008
#define OFF_TG 22208
#define OFF_TB 25088
#define OFF_R  27968
#define SMEM_FLOATS 28032
#define SMEM_BYTES (SMEM_FLOATS*4)

__global__ __launch_bounds__(256) void final_kernel(
    const float* __restrict__ x_in,
    const float* __restrict__ sgw, const float* __restrict__ sgb,
    const float* __restrict__ sbw, const float* __restrict__ sbb,
    const float* __restrict__ cgb, const float* __restrict__ cbb,
    const float* __restrict__ bgam, const float* __restrict__ bbet,
    float* __restrict__ out)
{
    extern __shared__ float sm[];
    float* sW  = sm;
    float* sA  = sm + OFF_A;
    float* sTg = sm + OFF_TG;
    float* sTb = sm + OFF_TB;
    unsigned char* sR = (unsigned char*)(sm + OFF_R);

    int t = threadIdx.x;
    int b = blockIdx.z;
    int ty0 = blockIdx.y * 8, tx0 = blockIdx.x * 16;
    int cg = t >> 4, pg = t & 15;
    int c0 = cg * 8;
    int py = pg >> 1, px0 = (pg & 1) * 8;

    // prologue: tables + region halo
    for (int idx = t; idx < 2880; idx += 256) {
        sTg[idx] = g_Tg[b*2880 + idx];
        sTb[idx] = g_Tb[b*2880 + idx];
    }
    for (int idx = t; idx < 200; idx += 256) {
        int yy = idx / 20, xx = idx - yy*20;
        int gy = ty0 + yy - 1, gx = tx0 + xx - 1;
        unsigned char r = 5;
        if (xx < 18 && (unsigned)gy < 128u && (unsigned)gx < 128u)
            r = g_rmap[(b << 14) + (gy << 7) + gx];
        sR[idx] = r;
    }

    float acc[8][8];
    #pragma unroll
    for (int i = 0; i < 8; ++i)
        #pragma unroll
        for (int j = 0; j < 8; ++j) acc[i][j] = 0.f;

    // main conv over 128 input channels, chunks of 16
    for (int cc = 0; cc < 8; ++cc) {
        int ci0 = cc * 16;
        __syncthreads();
        // stage weights: sW[(cin*9+tap)*132 + c128]
        for (int idx = t; idx < 18432; idx += 256) {
            int c128 = idx / 144; int rem = idx - c128*144;
            int cin = rem / 9;    int tap = rem - cin*9;
            const float* wsrc = (c128 < 64) ? sgw : sbw;
            sW[(cin*9 + tap)*132 + c128] =
                __ldg(&wsrc[(((c128 & 63)*128) + ci0 + cin)*9 + tap]);
        }
        // stage actv halo: sA[cin*200 + yy*20 + xx]
        for (int idx = t; idx < 2880; idx += 256) {
            int cin = idx / 180; int rem = idx - cin*180;
            int yy = rem / 18;   int xx = rem - yy*18;
            int gy = ty0 + yy - 1, gx = tx0 + xx - 1;
            float v = 0.f;
            if ((unsigned)gy < 128u && (unsigned)gx < 128u)
                v = g_actv[(((size_t)(b*128 + ci0 + cin)) << 14) + (gy << 7) + gx];
            sA[cin*200 + yy*20 + xx] = v;
        }
        __syncthreads();

        const float* aBase = sA + py*20 + px0;
        const float* wBase = sW + c0;
        #pragma unroll 1
        for (int cin = 0; cin < 16; ++cin) {
            const float* aC = aBase + cin*200;
            const float* wC = wBase + cin*9*132;
            #pragma unroll
            for (int dy = 0; dy < 3; ++dy) {
                float ar[10];
                #pragma unroll
                for (int q = 0; q < 10; ++q) ar[q] = aC[dy*20 + q];
                #pragma unroll
                for (int dx = 0; dx < 3; ++dx) {
                    const float* wp = wC + (dy*3 + dx)*132;
                    float wv[8];
                    #pragma unroll
                    for (int i = 0; i < 8; ++i) wv[i] = wp[i];
                    #pragma unroll
                    for (int i = 0; i < 8; ++i)
                        #pragma unroll
                        for (int j = 0; j < 8; ++j)
                            acc[i][j] = fmaf(wv[i], ar[dx + j], acc[i][j]);
                }
            }
        }
    }

    // epilogue: table gather + biases + sigmoid blend
    float ga = 1.f / (1.f + __expf(-__ldg(bgam)));
    float ba = 1.f / (1.f + __expf(-__ldg(bbet)));
    bool isG = (c0 < 64);
    int cB = c0 & 63;
    float blend = isG ? ga : ba;
    const float* sT    = isG ? sTg : sTb;
    const float* cbias = isG ? cgb : cbb;
    const float* spbias= isG ? sgb : sbb;

    #pragma unroll
    for (int i = 0; i < 8; ++i) {
        int c = cB + i;
        float cbv = __ldg(&cbias[c]);
        float sbv = __ldg(&spbias[c]);
        #pragma unroll
        for (int j = 0; j < 8; ++j) {
            float avg = cbv;
            #pragma unroll
            for (int tap = 0; tap < 9; ++tap) {
                int dy = tap / 3, dx = tap - dy*3;
                int rr = sR[(py + dy)*20 + px0 + j + dx];
                if (rr < 5) avg += sT[(tap*5 + rr)*64 + c];
            }
            float sp = acc[i][j] + sbv;
            acc[i][j] = blend*avg + (1.f - blend)*sp;
        }
    }

    __syncthreads();  // everyone done reading sW -> reuse as [128 ch][128 px] buffer
    #pragma unroll
    for (int i = 0; i < 8; ++i)
        #pragma unroll
        for (int j = 0; j < 8; ++j)
            sW[(c0 + i)*128 + py*16 + px0 + j] = acc[i][j];
    __syncthreads();

    // combine gamma/beta with instance-normed x
    for (int idx = t; idx < 8192; idx += 256) {
        int c = idx >> 7, pl = idx & 127;
        int y = ty0 + (pl >> 4), x = tx0 + (pl & 15);
        int ch = (b << 6) + c;
        float xv = x_in[((size_t)ch << 14) + (y << 7) + x];
        float xn = (xv - g_mean[ch]) * g_rsig[ch];
        float gf = sW[(c << 7) + pl];
        float bf = sW[((c + 64) << 7) + pl];
        out[((size_t)ch << 14) + (y << 7) + x] = fmaf(xn, gf, xn) + bf;
    }
}

// ---------------- launch ----------------
extern "C" void kernel_launch(void* const* d_in, const int* in_sizes, int n_in,
                              void* d_out, int out_size) {
    const float* x      = (const float*)d_in[0];
    const float* segmap = (const float*)d_in[1];
    const float* codes  = (const float*)d_in[2];
    const float* mask   = (const float*)d_in[3];
    const float* fc_w   = (const float*)d_in[4];
    const float* fc_b   = (const float*)d_in[5];
    const float* cgw    = (const float*)d_in[6];
    const float* cgb    = (const float*)d_in[7];
    const float* cbw    = (const float*)d_in[8];
    const float* cbb    = (const float*)d_in[9];
    const float* ssw    = (const float*)d_in[10];
    const float* ssb    = (const float*)d_in[11];
    const float* sgw    = (const float*)d_in[12];
    const float* sgb    = (const float*)d_in[13];
    const float* sbw    = (const float*)d_in[14];
    const float* sbb    = (const float*)d_in[15];
    const float* bgam   = (const float*)d_in[16];
    const float* bbet   = (const float*)d_in[17];
    float* out = (float*)d_out;

    cudaFuncSetAttribute(final_kernel, cudaFuncAttributeMaxDynamicSharedMemorySize, SMEM_BYTES);

    mu_kernel<<<B_*F_, 512>>>(codes, fc_w, fc_b);
    region_kernel<<<(B_*HH*WW + 255)/256, 256>>>(segmap);
    table_kernel<<<2880, 256>>>(cgw, cbw);
    stats_kernel<<<B_*C_, 256>>>(x);
    sconv_kernel<<<(B_*NH_*HH*WW + 255)/256, 256>>>(mask, ssw, ssb);

    dim3 grid(WW/16, HH/8, B_);
    final_kernel<<<grid, 256, SMEM_BYTES>>>(x, sgw, sgb, sbw, sbb,
                                            cgb, cbb, bgam, bbet, out);
}